// round 13
// baseline (speedup 1.0000x reference)
#include <cuda_runtime.h>

#define N_SAMP 384
#define M 12
#define NP 6
#define UC (M * NP)      // 72 complex entries per sample
#define NBLK 576         // 24 x 24 pair tiles
#define BBLK 48          // builder blocks; 768/48 = 16 samples each

typedef unsigned long long u64;

// Duplicated packed operand formats (built in-kernel by the first BBLK blocks):
// g_u1d entry e=(k*6+b): [2e]=(re,im)=bp  [2e+1]=(-im,re)=bn
// g_u2d entry e=(k*6+a): [2e]=(cre,cre)=aR [2e+1]=(cim,cim)=aI  (c = conj(U2))
__device__ __align__(16) float2 g_u1d[N_SAMP * UC * 2];
__device__ __align__(16) float2 g_u2d[N_SAMP * UC * 2];

// producer/consumer handshake; self-resetting across graph replays
__device__ unsigned g_cnt  = 0;
__device__ unsigned g_done = 0;

__device__ __forceinline__ float2 cmul(float2 a, float2 b) {
    return make_float2(a.x * b.x - a.y * b.y, a.x * b.y + a.y * b.x);
}

// ---- packed f32x2 helpers ----
__device__ __forceinline__ float2 upk(u64 d) {
    float2 r; asm("mov.b64 {%0,%1}, %2;" : "=f"(r.x), "=f"(r.y) : "l"(d)); return r;
}
__device__ __forceinline__ u64 ffma2(u64 a, u64 b, u64 c) {
    u64 d; asm("fma.rn.f32x2 %0, %1, %2, %3;" : "=l"(d) : "l"(a), "l"(b), "l"(c)); return d;
}
__device__ __forceinline__ u64 fmul2(u64 a, u64 b) {
    u64 d; asm("mul.rn.f32x2 %0, %1, %2;" : "=l"(d) : "l"(a), "l"(b)); return d;
}
__device__ __forceinline__ u64 fadd2(u64 a, u64 b) {
    u64 d; asm("add.rn.f32x2 %0, %1, %2;" : "=l"(d) : "l"(a), "l"(b)); return d;
}

#define SPV 73   // smem pitch in ulonglong2 (16B units, odd -> conflict-free)

__device__ __forceinline__ float2 prod6f(const float2* r) {
    float2 p01 = cmul(r[0], r[1]);
    float2 p23 = cmul(r[2], r[3]);
    float2 p45 = cmul(r[4], r[5]);
    return cmul(cmul(p01, p23), p45);
}

__global__ __launch_bounds__(256, 2) void fused_kernel(
    const float* __restrict__ x1, const float* __restrict__ x2,
    const float* __restrict__ A_re, const float* __restrict__ A_im,
    const float* __restrict__ B_re, const float* __restrict__ B_im,
    float* __restrict__ out)
{
    __shared__ __align__(16) ulonglong2 s1[16 * SPV];
    __shared__ __align__(16) ulonglong2 s2[16 * SPV];

    const int tid = threadIdx.x;
    const int bid = blockIdx.y * 24 + blockIdx.x;

    // ---------------- build phase: first BBLK blocks create packed U ----------
    if (bid < BBLK) {
        // overlay scratch on s1 (overwritten later, after the barrier)
        float2* ph = (float2*)s1;       // [16][12] phases
        float2* sA = ph + 16 * M;       // [12][12]
        float2* sB = sA + M * M;        // [12][6]

        for (int idx = tid; idx < M * M; idx += 256)
            sA[idx] = make_float2(A_re[idx], A_im[idx]);
        for (int idx = tid; idx < M * NP; idx += 256) {
            int b = idx / NP, c = idx - b * NP;
            sB[idx] = make_float2(B_re[b * M + c], B_im[b * M + c]);
        }
        for (int idx = tid; idx < 16 * M; idx += 256) {
            int si = idx / M, m = idx - si * M;
            int s  = bid * 16 + si;                       // 0..767
            float xv = (s < N_SAMP) ? x1[s * M + m] : x2[(s - N_SAMP) * M + m];
            float sn, cs;
            sincosf(xv, &sn, &cs);
            ph[idx] = make_float2(cs, sn);
        }
        __syncthreads();

        for (int e = tid; e < 16 * UC; e += 256) {
            int si = e / UC, t = e - si * UC;
            int a = t / NP, c = t - a * NP;
            int s = bid * 16 + si;
            float2 acc = make_float2(0.f, 0.f);
#pragma unroll
            for (int b = 0; b < M; ++b) {
                float2 tp = cmul(ph[si * M + b], sB[b * NP + c]);
                float2 Av = sA[a * M + b];
                acc.x += Av.x * tp.x - Av.y * tp.y;
                acc.y += Av.x * tp.y + Av.y * tp.x;
            }
            if (s < N_SAMP) {
                int base = (s * UC + t) * 2;
                g_u1d[base + 0] = make_float2(acc.x, acc.y);    // bp
                g_u1d[base + 1] = make_float2(-acc.y, acc.x);   // bn
            } else {
                int base = ((s - N_SAMP) * UC + t) * 2;
                g_u2d[base + 0] = make_float2(acc.x, acc.x);    // aR (conj re)
                g_u2d[base + 1] = make_float2(-acc.y, -acc.y);  // aI (conj im)
            }
        }
        __threadfence();
        __syncthreads();
        if (tid == 0) atomicAdd(&g_cnt, 1u);
    }

    // ---------------- barrier: wait for all builders --------------------------
    if (tid == 0) {
        while (*(volatile unsigned*)&g_cnt < (unsigned)BBLK) { }
    }
    __syncthreads();
    __threadfence();

    // ---------------- pair phase (identical to R12 best) ----------------------
    const int i0 = blockIdx.y * 16;
    const int j0 = blockIdx.x * 16;

    const ulonglong2* __restrict__ gu1 = (const ulonglong2*)g_u1d;
    const ulonglong2* __restrict__ gu2 = (const ulonglong2*)g_u2d;
    for (int e = tid; e < 16 * UC; e += 256) {
        int l = e / UC;
        int r = e - l * UC;
        s1[l * SPV + r] = gu1[(i0 + l) * UC + r];
        s2[l * SPV + r] = gu2[(j0 + l) * UC + r];
    }
    __syncthreads();

    const int lj = tid & 15;        // j fastest -> coalesced output
    const int li = tid >> 4;
    const ulonglong2* __restrict__ p1 = &s1[li * SPV];   // {bp, bn}
    const ulonglong2* __restrict__ p2 = &s2[lj * SPV];   // {aR, aI}

    u64 W[NP][NP];

    // k = 0 initializes W
    {
        ulonglong2 bb[NP];
#pragma unroll
        for (int b = 0; b < NP; ++b) bb[b] = p1[b];
#pragma unroll
        for (int a = 0; a < NP; ++a) {
            const ulonglong2 av = p2[a];
#pragma unroll
            for (int b = 0; b < NP; ++b)
                W[a][b] = ffma2(av.y, bb[b].y, fmul2(av.x, bb[b].x));
        }
    }

#pragma unroll
    for (int k = 1; k < M; ++k) {
        ulonglong2 bb[NP];
#pragma unroll
        for (int b = 0; b < NP; ++b) bb[b] = p1[k * NP + b];
#pragma unroll
        for (int a = 0; a < NP; ++a) {
            const ulonglong2 av = p2[k * NP + a];
#pragma unroll
            for (int b = 0; b < NP; ++b) {
                W[a][b] = ffma2(av.x, bb[b].x, W[a][b]);
                W[a][b] = ffma2(av.y, bb[b].y, W[a][b]);
            }
        }
    }

    // --- Glynn permanent, n=6, single Gray chain, FFMA-imm updates ---
    float2 r[NP];
#pragma unroll
    for (int j = 0; j < NP; ++j) {
        u64 t01 = fadd2(W[0][j], W[1][j]);
        u64 t23 = fadd2(W[2][j], W[3][j]);
        u64 t45 = fadd2(W[4][j], W[5][j]);
        r[j] = upk(fadd2(fadd2(t01, t23), t45));
    }

    float2 acc = prod6f(r);

#pragma unroll
    for (int t = 1; t < 32; ++t) {
        const int bit = (t & 1) ? 0 : ((t & 2) ? 1 : ((t & 4) ? 2 : ((t & 8) ? 3 : 4)));
        const int a   = bit + 1;                              // flipped row (1..5)
        const bool neg = (((t ^ (t >> 1)) >> bit) & 1) != 0;
        const float s2v = neg ? -2.0f : 2.0f;                 // fp32 immediate

#pragma unroll
        for (int j = 0; j < NP; ++j) {
            float2 w = upk(W[a][j]);
            r[j].x = fmaf(s2v, w.x, r[j].x);
            r[j].y = fmaf(s2v, w.y, r[j].y);
        }
        float2 p = prod6f(r);
        if (t & 1) { acc.x -= p.x; acc.y -= p.y; }            // parity (-1)^t
        else       { acc.x += p.x; acc.y += p.y; }
    }

    const float K = (acc.x * acc.x + acc.y * acc.y) * (1.0f / 1024.0f);
    out[(i0 + li) * N_SAMP + (j0 + lj)] = K;

    // ---------------- self-reset for the next graph replay ---------------------
    if (tid == 0) {
        unsigned f = atomicAdd(&g_done, 1u);
        if (f == (unsigned)(NBLK - 1)) {
            g_cnt  = 0u;
            g_done = 0u;
            __threadfence();
        }
    }
}

// ---------------------------------------------------------------------------
extern "C" void kernel_launch(void* const* d_in, const int* in_sizes, int n_in,
                              void* d_out, int out_size)
{
    const float* x1   = (const float*)d_in[0];
    const float* x2   = (const float*)d_in[1];
    const float* A_re = (const float*)d_in[2];
    const float* A_im = (const float*)d_in[3];
    const float* B_re = (const float*)d_in[4];
    const float* B_im = (const float*)d_in[5];

    dim3 grid(N_SAMP / 16, N_SAMP / 16);   // 24 x 24 = 576 blocks
    fused_kernel<<<grid, 256>>>(x1, x2, A_re, A_im, B_re, B_im, (float*)d_out);
}